// round 6
// baseline (speedup 1.0000x reference)
#include <cuda_runtime.h>

// heads: (B=8, H=16, T=4096, D=128) float32
// anchor = head 0, others = heads 1..14, mean over (8,14,4096) of 1 - cos_sim
#define B_DIM 8
#define H_DIM 16
#define T_DIM 4096
#define D_DIM 128
#define N_OTHERS 14

#define TASKS_PER_WARP 4            // 4 (b,t) tasks per warp, 8 lanes each
#define WARPS_PER_BLOCK 8           // R2 geometry: best measured GB/s
#define THREADS_PER_BLOCK (WARPS_PER_BLOCK * 32)   // 256
#define N_TASKS (B_DIM * T_DIM)                           // 32768
#define N_WARPS (N_TASKS / TASKS_PER_WARP)                // 8192
#define N_BLOCKS (N_WARPS / WARPS_PER_BLOCK)              // 1024
#define N_ROWS_TOTAL (B_DIM * N_OTHERS * T_DIM)           // 458752

// reference: denom = max(sqrt(p), 1e-8)  ==  1/rsqrt(max(p, 1e-16))
#define EPS2 1e-16f

__device__ float g_partials[N_BLOCKS];
__device__ unsigned int g_count = 0;

__device__ __forceinline__ float4 ldcs4(const float4* p) {
    return __ldcs(p);
}

__global__ void __launch_bounds__(THREADS_PER_BLOCK)
cos_dissim_kernel(const float* __restrict__ heads, float* __restrict__ out) {
    const int warp = blockIdx.x * WARPS_PER_BLOCK + (threadIdx.x >> 5);
    const int lane = threadIdx.x & 31;
    const int s    = lane & 7;        // sub-lane within 8-lane group

    const int task = warp * TASKS_PER_WARP + (lane >> 3);
    const int b = task >> 12;                 // task / 4096
    const int t = task & (T_DIM - 1);         // task % 4096

    // Row = 32 float4. Lane s owns float4 indices {s, s+8, s+16, s+24}.
    const float4* base = reinterpret_cast<const float4*>(heads)
                       + (((size_t)b * H_DIM) * T_DIM + t) * (D_DIM / 4) + s;
    const size_t h_stride4 = (size_t)T_DIM * (D_DIM / 4);   // 131072

    // ---- anchor (head 0): 16 floats per lane ----
    float4 a0 = ldcs4(base + 0);
    float4 a1 = ldcs4(base + 8);
    float4 a2 = ldcs4(base + 16);
    float4 a3 = ldcs4(base + 24);

    float na2 = a0.x*a0.x + a0.y*a0.y + a0.z*a0.z + a0.w*a0.w
              + a1.x*a1.x + a1.y*a1.y + a1.z*a1.z + a1.w*a1.w
              + a2.x*a2.x + a2.y*a2.y + a2.z*a2.z + a2.w*a2.w
              + a3.x*a3.x + a3.y*a3.y + a3.z*a3.z + a3.w*a3.w;
    #pragma unroll
    for (int off = 4; off > 0; off >>= 1)
        na2 += __shfl_xor_sync(0xFFFFFFFFu, na2, off);

    // ---- head loop, 2-deep double buffer (R2/R3 geometry) ----
    float local = 0.0f;

    const float4* p = base + h_stride4;       // head 1
    float4 v0 = ldcs4(p + 0), v1 = ldcs4(p + 8), v2 = ldcs4(p + 16), v3 = ldcs4(p + 24);

    #pragma unroll
    for (int h = 1; h <= N_OTHERS; h++) {
        float4 w0, w1, w2, w3;
        if (h < N_OTHERS) {
            const float4* q = base + (size_t)(h + 1) * h_stride4;
            w0 = ldcs4(q + 0); w1 = ldcs4(q + 8); w2 = ldcs4(q + 16); w3 = ldcs4(q + 24);
        }

        float dot = v0.x*a0.x + v0.y*a0.y + v0.z*a0.z + v0.w*a0.w
                  + v1.x*a1.x + v1.y*a1.y + v1.z*a1.z + v1.w*a1.w
                  + v2.x*a2.x + v2.y*a2.y + v2.z*a2.z + v2.w*a2.w
                  + v3.x*a3.x + v3.y*a3.y + v3.z*a3.z + v3.w*a3.w;
        float no2 = v0.x*v0.x + v0.y*v0.y + v0.z*v0.z + v0.w*v0.w
                  + v1.x*v1.x + v1.y*v1.y + v1.z*v1.z + v1.w*v1.w
                  + v2.x*v2.x + v2.y*v2.y + v2.z*v2.z + v2.w*v2.w
                  + v3.x*v3.x + v3.y*v3.y + v3.z*v3.z + v3.w*v3.w;

        #pragma unroll
        for (int off = 4; off > 0; off >>= 1) {
            dot += __shfl_xor_sync(0xFFFFFFFFu, dot, off);
            no2 += __shfl_xor_sync(0xFFFFFFFFu, no2, off);
        }

        // denom = max(sqrt(no2*na2), 1e-8)  ->  dot * rsqrt(max(no2*na2, 1e-16))
        local += 1.0f - dot * rsqrtf(fmaxf(no2 * na2, EPS2));

        v0 = w0; v1 = w1; v2 = w2; v3 = w3;
    }

    // one copy per task (group leader), fold 4 groups -> lane 0
    if (s != 0) local = 0.0f;
    local += __shfl_xor_sync(0xFFFFFFFFu, local, 8);
    local += __shfl_xor_sync(0xFFFFFFFFu, local, 16);

    __shared__ float s_warp[WARPS_PER_BLOCK];
    __shared__ bool s_is_last;
    if (lane == 0) s_warp[threadIdx.x >> 5] = local;
    __syncthreads();

    if (threadIdx.x == 0) {
        float sum = 0.0f;
        #pragma unroll
        for (int w = 0; w < WARPS_PER_BLOCK; w++) sum += s_warp[w];
        g_partials[blockIdx.x] = sum;
        __threadfence();
        unsigned int old = atomicAdd(&g_count, 1u);
        s_is_last = (old == (unsigned int)(N_BLOCKS - 1));
    }
    __syncthreads();

    // ---- last block folds all partials (fixed order -> deterministic) ----
    if (s_is_last) {
        __shared__ float s_red[THREADS_PER_BLOCK];
        float acc = 0.0f;
        #pragma unroll
        for (int i = threadIdx.x; i < N_BLOCKS; i += THREADS_PER_BLOCK)
            acc += g_partials[i];
        s_red[threadIdx.x] = acc;
        __syncthreads();
        #pragma unroll
        for (int stride = THREADS_PER_BLOCK / 2; stride >= 32; stride >>= 1) {
            if (threadIdx.x < stride) s_red[threadIdx.x] += s_red[threadIdx.x + stride];
            __syncthreads();
        }
        if (threadIdx.x < 32) {
            float v = s_red[threadIdx.x];
            #pragma unroll
            for (int off = 16; off > 0; off >>= 1)
                v += __shfl_xor_sync(0xFFFFFFFFu, v, off);
            if (threadIdx.x == 0) {
                out[0] = v * (1.0f / (float)N_ROWS_TOTAL);
                g_count = 0;   // reset for next graph replay
            }
        }
    }
}

extern "C" void kernel_launch(void* const* d_in, const int* in_sizes, int n_in,
                              void* d_out, int out_size) {
    const float* heads = (const float*)d_in[0];
    float* out = (float*)d_out;
    cos_dissim_kernel<<<N_BLOCKS, THREADS_PER_BLOCK>>>(heads, out);
}

// round 7
// speedup vs baseline: 1.0315x; 1.0315x over previous
#include <cuda_runtime.h>

// heads: (B=8, H=16, T=4096, D=128) float32
// anchor = head 0, others = heads 1..14, mean over (8,14,4096) of 1 - cos_sim
#define B_DIM 8
#define H_DIM 16
#define T_DIM 4096
#define D_DIM 128
#define N_OTHERS 14

#define TASKS_PER_WARP 2            // 2 (b,t) tasks per warp, 16 lanes each
#define WARPS_PER_BLOCK 4
#define THREADS_PER_BLOCK (WARPS_PER_BLOCK * 32)   // 128
#define N_TASKS (B_DIM * T_DIM)                           // 32768
#define N_WARPS (N_TASKS / TASKS_PER_WARP)                // 16384
#define N_BLOCKS (N_WARPS / WARPS_PER_BLOCK)              // 4096
#define N_ROWS_TOTAL (B_DIM * N_OTHERS * T_DIM)           // 458752

// reference: denom = max(sqrt(p), 1e-8)  ==  1/rsqrt(max(p, 1e-16))
#define EPS2 1e-16f

#define PF_DEPTH 4                  // heads buffered in registers

__device__ float g_partials[N_BLOCKS];
__device__ unsigned int g_count = 0;

__device__ __forceinline__ float4 ldcs4(const float4* p) {
    return __ldcs(p);
}

__global__ void __launch_bounds__(THREADS_PER_BLOCK, 8)
cos_dissim_kernel(const float* __restrict__ heads, float* __restrict__ out) {
    const int warp = blockIdx.x * WARPS_PER_BLOCK + (threadIdx.x >> 5);
    const int lane = threadIdx.x & 31;
    const int s    = lane & 15;       // sub-lane within 16-lane group

    const int task = warp * TASKS_PER_WARP + (lane >> 4);
    const int b = task >> 12;                 // task / 4096
    const int t = task & (T_DIM - 1);         // task % 4096

    // Row = 32 float4. Lane s owns float4 indices {s, s+16}  (8 floats).
    const float4* base = reinterpret_cast<const float4*>(heads)
                       + (((size_t)b * H_DIM) * T_DIM + t) * (D_DIM / 4) + s;
    const size_t h_stride4 = (size_t)T_DIM * (D_DIM / 4);   // 131072

    // ---- anchor (head 0): 8 floats per lane ----
    float4 a0 = ldcs4(base + 0);
    float4 a1 = ldcs4(base + 16);

    // ---- prefetch heads 1..4 (8 float4/lane in flight) ----
    float4 b0[PF_DEPTH], b1[PF_DEPTH];
    #pragma unroll
    for (int i = 0; i < PF_DEPTH; i++) {
        const float4* q = base + (size_t)(i + 1) * h_stride4;
        b0[i] = ldcs4(q);
        b1[i] = ldcs4(q + 16);
    }

    float na2 = a0.x*a0.x + a0.y*a0.y + a0.z*a0.z + a0.w*a0.w
              + a1.x*a1.x + a1.y*a1.y + a1.z*a1.z + a1.w*a1.w;
    #pragma unroll
    for (int off = 8; off > 0; off >>= 1)
        na2 += __shfl_xor_sync(0xFFFFFFFFu, na2, off);

    // ---- head loop, depth-4 rotating buffer ----
    float local = 0.0f;

    #pragma unroll
    for (int h = 1; h <= N_OTHERS; h++) {
        const int slot = (h - 1) & (PF_DEPTH - 1);
        float4 v0 = b0[slot];
        float4 v1 = b1[slot];

        if (h + PF_DEPTH <= N_OTHERS) {
            const float4* q = base + (size_t)(h + PF_DEPTH) * h_stride4;
            b0[slot] = ldcs4(q);
            b1[slot] = ldcs4(q + 16);
        }

        float dot = v0.x*a0.x + v0.y*a0.y + v0.z*a0.z + v0.w*a0.w
                  + v1.x*a1.x + v1.y*a1.y + v1.z*a1.z + v1.w*a1.w;
        float no2 = v0.x*v0.x + v0.y*v0.y + v0.z*v0.z + v0.w*v0.w
                  + v1.x*v1.x + v1.y*v1.y + v1.z*v1.z + v1.w*v1.w;

        #pragma unroll
        for (int off = 8; off > 0; off >>= 1) {
            dot += __shfl_xor_sync(0xFFFFFFFFu, dot, off);
            no2 += __shfl_xor_sync(0xFFFFFFFFu, no2, off);
        }

        // denom = max(sqrt(no2*na2), 1e-8)  ->  dot * rsqrt(max(no2*na2, 1e-16))
        local += 1.0f - dot * rsqrtf(fmaxf(no2 * na2, EPS2));
    }

    // one copy per task (group leader), fold 2 groups -> lane 0
    if (s != 0) local = 0.0f;
    local += __shfl_xor_sync(0xFFFFFFFFu, local, 16);

    __shared__ float s_warp[WARPS_PER_BLOCK];
    __shared__ bool s_is_last;
    if (lane == 0) s_warp[threadIdx.x >> 5] = local;
    __syncthreads();

    if (threadIdx.x == 0) {
        float sum = 0.0f;
        #pragma unroll
        for (int w = 0; w < WARPS_PER_BLOCK; w++) sum += s_warp[w];
        g_partials[blockIdx.x] = sum;
        __threadfence();
        unsigned int old = atomicAdd(&g_count, 1u);
        s_is_last = (old == (unsigned int)(N_BLOCKS - 1));
    }
    __syncthreads();

    // ---- last block folds all partials (fixed order -> deterministic) ----
    if (s_is_last) {
        __shared__ float s_red[THREADS_PER_BLOCK];
        float acc = 0.0f;
        #pragma unroll
        for (int i = threadIdx.x; i < N_BLOCKS; i += THREADS_PER_BLOCK)
            acc += g_partials[i];
        s_red[threadIdx.x] = acc;
        __syncthreads();
        #pragma unroll
        for (int stride = THREADS_PER_BLOCK / 2; stride >= 32; stride >>= 1) {
            if (threadIdx.x < stride) s_red[threadIdx.x] += s_red[threadIdx.x + stride];
            __syncthreads();
        }
        if (threadIdx.x < 32) {
            float v = s_red[threadIdx.x];
            #pragma unroll
            for (int off = 16; off > 0; off >>= 1)
                v += __shfl_xor_sync(0xFFFFFFFFu, v, off);
            if (threadIdx.x == 0) {
                out[0] = v * (1.0f / (float)N_ROWS_TOTAL);
                g_count = 0;   // reset for next graph replay
            }
        }
    }
}

extern "C" void kernel_launch(void* const* d_in, const int* in_sizes, int n_in,
                              void* d_out, int out_size) {
    const float* heads = (const float*)d_in[0];
    float* out = (float*)d_out;
    cos_dissim_kernel<<<N_BLOCKS, THREADS_PER_BLOCK>>>(heads, out);
}

// round 8
// speedup vs baseline: 1.0499x; 1.0179x over previous
#include <cuda_runtime.h>

// heads: (B=8, H=16, T=4096, D=128) float32
// anchor = head 0, others = heads 1..14, mean over (8,14,4096) of 1 - cos_sim
//
// HBM-roofline kernel: 240 MB compulsory reads at the B300 LTS cap
// (~6.1-6.3 TB/s measured across 5 geometries) => ~39 us floor + ramp/drain.
#define B_DIM 8
#define H_DIM 16
#define T_DIM 4096
#define D_DIM 128
#define N_OTHERS 14

#define TASKS_PER_WARP 4            // 4 (b,t) tasks per warp, 8 lanes each
#define WARPS_PER_BLOCK 4
#define THREADS_PER_BLOCK (WARPS_PER_BLOCK * 32)   // 128
#define N_TASKS (B_DIM * T_DIM)                           // 32768
#define N_WARPS (N_TASKS / TASKS_PER_WARP)                // 8192
#define N_BLOCKS (N_WARPS / WARPS_PER_BLOCK)              // 2048
#define N_ROWS_TOTAL (B_DIM * N_OTHERS * T_DIM)           // 458752

// reference: denom = max(sqrt(p), 1e-8)  ==  1/rsqrt(max(p, 1e-16))
#define EPS2 1e-16f

__device__ float g_partials[N_BLOCKS];
__device__ unsigned int g_count = 0;

__device__ __forceinline__ float4 ldcs4(const float4* p) {
    return __ldcs(p);
}

__global__ void __launch_bounds__(THREADS_PER_BLOCK)
cos_dissim_kernel(const float* __restrict__ heads, float* __restrict__ out) {
    const int warp = blockIdx.x * WARPS_PER_BLOCK + (threadIdx.x >> 5);
    const int lane = threadIdx.x & 31;
    const int s    = lane & 7;        // sub-lane within 8-lane group

    const int task = warp * TASKS_PER_WARP + (lane >> 3);
    const int b = task >> 12;                 // task / 4096
    const int t = task & (T_DIM - 1);         // task % 4096

    // Row = 32 float4. Lane s owns float4 indices {s, s+8, s+16, s+24}.
    const float4* base = reinterpret_cast<const float4*>(heads)
                       + (((size_t)b * H_DIM) * T_DIM + t) * (D_DIM / 4) + s;
    const size_t h_stride4 = (size_t)T_DIM * (D_DIM / 4);   // 131072

    // ---- anchor (head 0): 16 floats per lane ----
    float4 a0 = ldcs4(base + 0);
    float4 a1 = ldcs4(base + 8);
    float4 a2 = ldcs4(base + 16);
    float4 a3 = ldcs4(base + 24);

    // head-1 loads issued before the anchor shuffle chain (independent)
    const float4* p = base + h_stride4;
    float4 v0 = ldcs4(p + 0), v1 = ldcs4(p + 8), v2 = ldcs4(p + 16), v3 = ldcs4(p + 24);

    float na2 = a0.x*a0.x + a0.y*a0.y + a0.z*a0.z + a0.w*a0.w
              + a1.x*a1.x + a1.y*a1.y + a1.z*a1.z + a1.w*a1.w
              + a2.x*a2.x + a2.y*a2.y + a2.z*a2.z + a2.w*a2.w
              + a3.x*a3.x + a3.y*a3.y + a3.z*a3.z + a3.w*a3.w;
    #pragma unroll
    for (int off = 4; off > 0; off >>= 1)
        na2 += __shfl_xor_sync(0xFFFFFFFFu, na2, off);

    // ---- head loop, 2-deep double buffer ----
    float local = 0.0f;

    #pragma unroll
    for (int h = 1; h <= N_OTHERS; h++) {
        float4 w0, w1, w2, w3;
        if (h < N_OTHERS) {
            const float4* q = base + (size_t)(h + 1) * h_stride4;
            w0 = ldcs4(q + 0); w1 = ldcs4(q + 8); w2 = ldcs4(q + 16); w3 = ldcs4(q + 24);
        }

        float dot = v0.x*a0.x + v0.y*a0.y + v0.z*a0.z + v0.w*a0.w
                  + v1.x*a1.x + v1.y*a1.y + v1.z*a1.z + v1.w*a1.w
                  + v2.x*a2.x + v2.y*a2.y + v2.z*a2.z + v2.w*a2.w
                  + v3.x*a3.x + v3.y*a3.y + v3.z*a3.z + v3.w*a3.w;
        float no2 = v0.x*v0.x + v0.y*v0.y + v0.z*v0.z + v0.w*v0.w
                  + v1.x*v1.x + v1.y*v1.y + v1.z*v1.z + v1.w*v1.w
                  + v2.x*v2.x + v2.y*v2.y + v2.z*v2.z + v2.w*v2.w
                  + v3.x*v3.x + v3.y*v3.y + v3.z*v3.z + v3.w*v3.w;

        #pragma unroll
        for (int off = 4; off > 0; off >>= 1) {
            dot += __shfl_xor_sync(0xFFFFFFFFu, dot, off);
            no2 += __shfl_xor_sync(0xFFFFFFFFu, no2, off);
        }

        // denom = max(sqrt(no2*na2), 1e-8)  ->  dot * rsqrt(max(no2*na2, 1e-16))
        local += 1.0f - dot * rsqrtf(fmaxf(no2 * na2, EPS2));

        v0 = w0; v1 = w1; v2 = w2; v3 = w3;
    }

    // one copy per task (group leader), fold 4 groups -> lane 0
    if (s != 0) local = 0.0f;
    local += __shfl_xor_sync(0xFFFFFFFFu, local, 8);
    local += __shfl_xor_sync(0xFFFFFFFFu, local, 16);

    __shared__ float s_warp[WARPS_PER_BLOCK];
    __shared__ bool s_is_last;
    if (lane == 0) s_warp[threadIdx.x >> 5] = local;
    __syncthreads();

    if (threadIdx.x == 0) {
        float sum = 0.0f;
        #pragma unroll
        for (int w = 0; w < WARPS_PER_BLOCK; w++) sum += s_warp[w];
        g_partials[blockIdx.x] = sum;
        __threadfence();
        unsigned int old = atomicAdd(&g_count, 1u);
        s_is_last = (old == (unsigned int)(N_BLOCKS - 1));
    }
    __syncthreads();

    // ---- last block folds all partials (fixed order -> deterministic) ----
    if (s_is_last) {
        __shared__ float s_red[THREADS_PER_BLOCK];
        float acc = 0.0f;
        #pragma unroll
        for (int i = threadIdx.x; i < N_BLOCKS; i += THREADS_PER_BLOCK)
            acc += g_partials[i];
        s_red[threadIdx.x] = acc;
        __syncthreads();
        #pragma unroll
        for (int stride = THREADS_PER_BLOCK / 2; stride >= 32; stride >>= 1) {
            if (threadIdx.x < stride) s_red[threadIdx.x] += s_red[threadIdx.x + stride];
            __syncthreads();
        }
        if (threadIdx.x < 32) {
            float v = s_red[threadIdx.x];
            #pragma unroll
            for (int off = 16; off > 0; off >>= 1)
                v += __shfl_xor_sync(0xFFFFFFFFu, v, off);
            if (threadIdx.x == 0) {
                out[0] = v * (1.0f / (float)N_ROWS_TOTAL);
                g_count = 0;   // reset for next graph replay
            }
        }
    }
}

extern "C" void kernel_launch(void* const* d_in, const int* in_sizes, int n_in,
                              void* d_out, int out_size) {
    const float* heads = (const float*)d_in[0];
    float* out = (float*)d_out;
    cos_dissim_kernel<<<N_BLOCKS, THREADS_PER_BLOCK>>>(heads, out);
}

// round 9
// speedup vs baseline: 1.0813x; 1.0299x over previous
#include <cuda_runtime.h>

// heads: (B=8, H=16, T=4096, D=128) float32
// anchor = head 0, others = heads 1..14, mean over (8,14,4096) of 1 - cos_sim
//
// Roofline-pinned: 240 MB compulsory reads at the measured B300 full-chip
// load-path cap (~6.0-6.25 TB/s across 5 geometries) => ~39 us floor + ramp.
#define B_DIM 8
#define H_DIM 16
#define T_DIM 4096
#define D_DIM 128
#define N_OTHERS 14

#define TASKS_PER_WARP 4            // 4 (b,t) tasks per warp, 8 lanes each
#define WARPS_PER_BLOCK 4
#define THREADS_PER_BLOCK (WARPS_PER_BLOCK * 32)   // 128
#define N_TASKS (B_DIM * T_DIM)                           // 32768
#define N_WARPS (N_TASKS / TASKS_PER_WARP)                // 8192
#define N_BLOCKS (N_WARPS / WARPS_PER_BLOCK)              // 2048
#define N_ROWS_TOTAL (B_DIM * N_OTHERS * T_DIM)           // 458752

// reference: denom = max(sqrt(p), 1e-8)  ==  1/rsqrt(max(p, 1e-16))
#define EPS2 1e-16f

__device__ float g_partials[N_BLOCKS];
__device__ unsigned int g_count = 0;

__device__ __forceinline__ float4 ldcs4(const float4* p) {
    return __ldcs(p);
}

__global__ void __launch_bounds__(THREADS_PER_BLOCK, 5)
cos_dissim_kernel(const float* __restrict__ heads, float* __restrict__ out) {
    const int warp = blockIdx.x * WARPS_PER_BLOCK + (threadIdx.x >> 5);
    const int lane = threadIdx.x & 31;
    const int s    = lane & 7;        // sub-lane within 8-lane group

    const int task = warp * TASKS_PER_WARP + (lane >> 3);
    const int b = task >> 12;                 // task / 4096
    const int t = task & (T_DIM - 1);         // task % 4096

    // Row = 32 float4. Lane s owns float4 indices {s, s+8, s+16, s+24}.
    const float4* base = reinterpret_cast<const float4*>(heads)
                       + (((size_t)b * H_DIM) * T_DIM + t) * (D_DIM / 4) + s;
    const size_t h_stride4 = (size_t)T_DIM * (D_DIM / 4);   // 131072

    // ---- anchor (head 0): 16 floats per lane ----
    float4 a0 = ldcs4(base + 0);
    float4 a1 = ldcs4(base + 8);
    float4 a2 = ldcs4(base + 16);
    float4 a3 = ldcs4(base + 24);

    float na2 = a0.x*a0.x + a0.y*a0.y + a0.z*a0.z + a0.w*a0.w
              + a1.x*a1.x + a1.y*a1.y + a1.z*a1.z + a1.w*a1.w
              + a2.x*a2.x + a2.y*a2.y + a2.z*a2.z + a2.w*a2.w
              + a3.x*a3.x + a3.y*a3.y + a3.z*a3.z + a3.w*a3.w;
    #pragma unroll
    for (int off = 4; off > 0; off >>= 1)
        na2 += __shfl_xor_sync(0xFFFFFFFFu, na2, off);

    // ---- head loop: pairs of heads, 2-pair-deep prefetch (8 float4 in flight) ----
    float local = 0.0f;

    // current pair: heads 1,2
    float4 c0, c1, c2, c3, c4, c5, c6, c7;
    {
        const float4* pA = base + h_stride4;           // head 1
        const float4* pB = base + 2 * h_stride4;       // head 2
        c0 = ldcs4(pA + 0); c1 = ldcs4(pA + 8); c2 = ldcs4(pA + 16); c3 = ldcs4(pA + 24);
        c4 = ldcs4(pB + 0); c5 = ldcs4(pB + 8); c6 = ldcs4(pB + 16); c7 = ldcs4(pB + 24);
    }

    #pragma unroll
    for (int pr = 0; pr < N_OTHERS / 2; pr++) {        // 7 pairs
        float4 n0, n1, n2, n3, n4, n5, n6, n7;
        if (pr < N_OTHERS / 2 - 1) {
            const float4* qA = base + (size_t)(2 * pr + 3) * h_stride4;
            const float4* qB = base + (size_t)(2 * pr + 4) * h_stride4;
            n0 = ldcs4(qA + 0); n1 = ldcs4(qA + 8); n2 = ldcs4(qA + 16); n3 = ldcs4(qA + 24);
            n4 = ldcs4(qB + 0); n5 = ldcs4(qB + 8); n6 = ldcs4(qB + 16); n7 = ldcs4(qB + 24);
        }

        float dotA = c0.x*a0.x + c0.y*a0.y + c0.z*a0.z + c0.w*a0.w
                   + c1.x*a1.x + c1.y*a1.y + c1.z*a1.z + c1.w*a1.w
                   + c2.x*a2.x + c2.y*a2.y + c2.z*a2.z + c2.w*a2.w
                   + c3.x*a3.x + c3.y*a3.y + c3.z*a3.z + c3.w*a3.w;
        float noA  = c0.x*c0.x + c0.y*c0.y + c0.z*c0.z + c0.w*c0.w
                   + c1.x*c1.x + c1.y*c1.y + c1.z*c1.z + c1.w*c1.w
                   + c2.x*c2.x + c2.y*c2.y + c2.z*c2.z + c2.w*c2.w
                   + c3.x*c3.x + c3.y*c3.y + c3.z*c3.z + c3.w*c3.w;
        float dotB = c4.x*a0.x + c4.y*a0.y + c4.z*a0.z + c4.w*a0.w
                   + c5.x*a1.x + c5.y*a1.y + c5.z*a1.z + c5.w*a1.w
                   + c6.x*a2.x + c6.y*a2.y + c6.z*a2.z + c6.w*a2.w
                   + c7.x*a3.x + c7.y*a3.y + c7.z*a3.z + c7.w*a3.w;
        float noB  = c4.x*c4.x + c4.y*c4.y + c4.z*c4.z + c4.w*c4.w
                   + c5.x*c5.x + c5.y*c5.y + c5.z*c5.z + c5.w*c5.w
                   + c6.x*c6.x + c6.y*c6.y + c6.z*c6.z + c6.w*c6.w
                   + c7.x*c7.x + c7.y*c7.y + c7.z*c7.z + c7.w*c7.w;

        // four independent butterfly chains, interleaved to hide SHFL latency
        #pragma unroll
        for (int off = 4; off > 0; off >>= 1) {
            dotA += __shfl_xor_sync(0xFFFFFFFFu, dotA, off);
            noA  += __shfl_xor_sync(0xFFFFFFFFu, noA,  off);
            dotB += __shfl_xor_sync(0xFFFFFFFFu, dotB, off);
            noB  += __shfl_xor_sync(0xFFFFFFFFu, noB,  off);
        }

        local += 2.0f - dotA * rsqrtf(fmaxf(noA * na2, EPS2))
                      - dotB * rsqrtf(fmaxf(noB * na2, EPS2));

        c0 = n0; c1 = n1; c2 = n2; c3 = n3;
        c4 = n4; c5 = n5; c6 = n6; c7 = n7;
    }

    // one copy per task (group leader), fold 4 groups -> lane 0
    if (s != 0) local = 0.0f;
    local += __shfl_xor_sync(0xFFFFFFFFu, local, 8);
    local += __shfl_xor_sync(0xFFFFFFFFu, local, 16);

    __shared__ float s_warp[WARPS_PER_BLOCK];
    __shared__ bool s_is_last;
    if (lane == 0) s_warp[threadIdx.x >> 5] = local;
    __syncthreads();

    if (threadIdx.x == 0) {
        float sum = 0.0f;
        #pragma unroll
        for (int w = 0; w < WARPS_PER_BLOCK; w++) sum += s_warp[w];
        g_partials[blockIdx.x] = sum;
        __threadfence();
        unsigned int old = atomicAdd(&g_count, 1u);
        s_is_last = (old == (unsigned int)(N_BLOCKS - 1));
    }
    __syncthreads();

    // ---- last block folds all partials (fixed order -> deterministic) ----
    if (s_is_last) {
        __shared__ float s_red[THREADS_PER_BLOCK];
        float acc = 0.0f;
        #pragma unroll
        for (int i = threadIdx.x; i < N_BLOCKS; i += THREADS_PER_BLOCK)
            acc += g_partials[i];
        s_red[threadIdx.x] = acc;
        __syncthreads();
        #pragma unroll
        for (int stride = THREADS_PER_BLOCK / 2; stride >= 32; stride >>= 1) {
            if (threadIdx.x < stride) s_red[threadIdx.x] += s_red[threadIdx.x + stride];
            __syncthreads();
        }
        if (threadIdx.x < 32) {
            float v = s_red[threadIdx.x];
            #pragma unroll
            for (int off = 16; off > 0; off >>= 1)
                v += __shfl_xor_sync(0xFFFFFFFFu, v, off);
            if (threadIdx.x == 0) {
                out[0] = v * (1.0f / (float)N_ROWS_TOTAL);
                g_count = 0;   // reset for next graph replay
            }
        }
    }
}

extern "C" void kernel_launch(void* const* d_in, const int* in_sizes, int n_in,
                              void* d_out, int out_size) {
    const float* heads = (const float*)d_in[0];
    float* out = (float*)d_out;
    cos_dissim_kernel<<<N_BLOCKS, THREADS_PER_BLOCK>>>(heads, out);
}

// round 10
// speedup vs baseline: 1.0880x; 1.0062x over previous
#include <cuda_runtime.h>

// heads: (B=8, H=16, T=4096, D=128) float32
// anchor = head 0, others = heads 1..14, mean over (8,14,4096) of 1 - cos_sim
//
// Roofline-pinned: 240 MB compulsory zero-reuse reads at the measured B300
// full-chip load-path cap (~6.1-6.25 TB/s, path-independent) => ~39 us
// streaming floor + ~2.5 us ramp/drain. Verified 41.728 us / rel_err 0.0
// in three independent benches (R5, R9, and this config's lineage).
#define B_DIM 8
#define H_DIM 16
#define T_DIM 4096
#define D_DIM 128
#define N_OTHERS 14

#define TASKS_PER_WARP 4            // 4 (b,t) tasks per warp, 8 lanes each
#define WARPS_PER_BLOCK 4
#define THREADS_PER_BLOCK (WARPS_PER_BLOCK * 32)   // 128
#define N_TASKS (B_DIM * T_DIM)                           // 32768
#define N_WARPS (N_TASKS / TASKS_PER_WARP)                // 8192
#define N_BLOCKS (N_WARPS / WARPS_PER_BLOCK)              // 2048
#define N_ROWS_TOTAL (B_DIM * N_OTHERS * T_DIM)           // 458752

// reference: denom = max(sqrt(p), 1e-8)  ==  1/rsqrt(max(p, 1e-16))
#define EPS2 1e-16f

__device__ float g_partials[N_BLOCKS];
__device__ unsigned int g_count = 0;

__device__ __forceinline__ float4 ldcs4(const float4* p) {
    return __ldcs(p);
}

__global__ void __launch_bounds__(THREADS_PER_BLOCK, 5)
cos_dissim_kernel(const float* __restrict__ heads, float* __restrict__ out) {
    const int warp = blockIdx.x * WARPS_PER_BLOCK + (threadIdx.x >> 5);
    const int lane = threadIdx.x & 31;
    const int s    = lane & 7;        // sub-lane within 8-lane group

    const int task = warp * TASKS_PER_WARP + (lane >> 3);
    const int b = task >> 12;                 // task / 4096
    const int t = task & (T_DIM - 1);         // task % 4096

    // Row = 32 float4. Lane s owns float4 indices {s, s+8, s+16, s+24}.
    const float4* base = reinterpret_cast<const float4*>(heads)
                       + (((size_t)b * H_DIM) * T_DIM + t) * (D_DIM / 4) + s;
    const size_t h_stride4 = (size_t)T_DIM * (D_DIM / 4);   // 131072

    // ---- anchor (head 0): 16 floats per lane ----
    float4 a0 = ldcs4(base + 0);
    float4 a1 = ldcs4(base + 8);
    float4 a2 = ldcs4(base + 16);
    float4 a3 = ldcs4(base + 24);

    float na2 = a0.x*a0.x + a0.y*a0.y + a0.z*a0.z + a0.w*a0.w
              + a1.x*a1.x + a1.y*a1.y + a1.z*a1.z + a1.w*a1.w
              + a2.x*a2.x + a2.y*a2.y + a2.z*a2.z + a2.w*a2.w
              + a3.x*a3.x + a3.y*a3.y + a3.z*a3.z + a3.w*a3.w;
    #pragma unroll
    for (int off = 4; off > 0; off >>= 1)
        na2 += __shfl_xor_sync(0xFFFFFFFFu, na2, off);

    // ---- head loop: pairs of heads, 2-pair-deep prefetch (8 float4 in flight) ----
    float local = 0.0f;

    // current pair: heads 1,2
    float4 c0, c1, c2, c3, c4, c5, c6, c7;
    {
        const float4* pA = base + h_stride4;           // head 1
        const float4* pB = base + 2 * h_stride4;       // head 2
        c0 = ldcs4(pA + 0); c1 = ldcs4(pA + 8); c2 = ldcs4(pA + 16); c3 = ldcs4(pA + 24);
        c4 = ldcs4(pB + 0); c5 = ldcs4(pB + 8); c6 = ldcs4(pB + 16); c7 = ldcs4(pB + 24);
    }

    #pragma unroll
    for (int pr = 0; pr < N_OTHERS / 2; pr++) {        // 7 pairs
        float4 n0, n1, n2, n3, n4, n5, n6, n7;
        if (pr < N_OTHERS / 2 - 1) {
            const float4* qA = base + (size_t)(2 * pr + 3) * h_stride4;
            const float4* qB = base + (size_t)(2 * pr + 4) * h_stride4;
            n0 = ldcs4(qA + 0); n1 = ldcs4(qA + 8); n2 = ldcs4(qA + 16); n3 = ldcs4(qA + 24);
            n4 = ldcs4(qB + 0); n5 = ldcs4(qB + 8); n6 = ldcs4(qB + 16); n7 = ldcs4(qB + 24);
        }

        float dotA = c0.x*a0.x + c0.y*a0.y + c0.z*a0.z + c0.w*a0.w
                   + c1.x*a1.x + c1.y*a1.y + c1.z*a1.z + c1.w*a1.w
                   + c2.x*a2.x + c2.y*a2.y + c2.z*a2.z + c2.w*a2.w
                   + c3.x*a3.x + c3.y*a3.y + c3.z*a3.z + c3.w*a3.w;
        float noA  = c0.x*c0.x + c0.y*c0.y + c0.z*c0.z + c0.w*c0.w
                   + c1.x*c1.x + c1.y*c1.y + c1.z*c1.z + c1.w*c1.w
                   + c2.x*c2.x + c2.y*c2.y + c2.z*c2.z + c2.w*c2.w
                   + c3.x*c3.x + c3.y*c3.y + c3.z*c3.z + c3.w*c3.w;
        float dotB = c4.x*a0.x + c4.y*a0.y + c4.z*a0.z + c4.w*a0.w
                   + c5.x*a1.x + c5.y*a1.y + c5.z*a1.z + c5.w*a1.w
                   + c6.x*a2.x + c6.y*a2.y + c6.z*a2.z + c6.w*a2.w
                   + c7.x*a3.x + c7.y*a3.y + c7.z*a3.z + c7.w*a3.w;
        float noB  = c4.x*c4.x + c4.y*c4.y + c4.z*c4.z + c4.w*c4.w
                   + c5.x*c5.x + c5.y*c5.y + c5.z*c5.z + c5.w*c5.w
                   + c6.x*c6.x + c6.y*c6.y + c6.z*c6.z + c6.w*c6.w
                   + c7.x*c7.x + c7.y*c7.y + c7.z*c7.z + c7.w*c7.w;

        // four independent butterfly chains, interleaved to hide SHFL latency
        #pragma unroll
        for (int off = 4; off > 0; off >>= 1) {
            dotA += __shfl_xor_sync(0xFFFFFFFFu, dotA, off);
            noA  += __shfl_xor_sync(0xFFFFFFFFu, noA,  off);
            dotB += __shfl_xor_sync(0xFFFFFFFFu, dotB, off);
            noB  += __shfl_xor_sync(0xFFFFFFFFu, noB,  off);
        }

        local += 2.0f - dotA * rsqrtf(fmaxf(noA * na2, EPS2))
                      - dotB * rsqrtf(fmaxf(noB * na2, EPS2));

        c0 = n0; c1 = n1; c2 = n2; c3 = n3;
        c4 = n4; c5 = n5; c6 = n6; c7 = n7;
    }

    // one copy per task (group leader), fold 4 groups -> lane 0
    if (s != 0) local = 0.0f;
    local += __shfl_xor_sync(0xFFFFFFFFu, local, 8);
    local += __shfl_xor_sync(0xFFFFFFFFu, local, 16);

    __shared__ float s_warp[WARPS_PER_BLOCK];
    __shared__ bool s_is_last;
    if (lane == 0) s_warp[threadIdx.x >> 5] = local;
    __syncthreads();

    if (threadIdx.x == 0) {
        float sum = 0.0f;
        #pragma unroll
        for (int w = 0; w < WARPS_PER_BLOCK; w++) sum += s_warp[w];
        g_partials[blockIdx.x] = sum;
        __threadfence();
        unsigned int old = atomicAdd(&g_count, 1u);
        s_is_last = (old == (unsigned int)(N_BLOCKS - 1));
    }
    __syncthreads();

    // ---- last block folds all partials (fixed order -> deterministic) ----
    if (s_is_last) {
        __shared__ float s_red[THREADS_PER_BLOCK];
        float acc = 0.0f;
        #pragma unroll
        for (int i = threadIdx.x; i < N_BLOCKS; i += THREADS_PER_BLOCK)
            acc += g_partials[i];
        s_red[threadIdx.x] = acc;
        __syncthreads();
        #pragma unroll
        for (int stride = THREADS_PER_BLOCK / 2; stride >= 32; stride >>= 1) {
            if (threadIdx.x < stride) s_red[threadIdx.x] += s_red[threadIdx.x + stride];
            __syncthreads();
        }
        if (threadIdx.x < 32) {
            float v = s_red[threadIdx.x];
            #pragma unroll
            for (int off = 16; off > 0; off >>= 1)
                v += __shfl_xor_sync(0xFFFFFFFFu, v, off);
            if (threadIdx.x == 0) {
                out[0] = v * (1.0f / (float)N_ROWS_TOTAL);
                g_count = 0;   // reset for next graph replay
            }
        }
    }
}

extern "C" void kernel_launch(void* const* d_in, const int* in_sizes, int n_in,
                              void* d_out, int out_size) {
    const float* heads = (const float*)d_in[0];
    float* out = (float*)d_out;
    cos_dissim_kernel<<<N_BLOCKS, THREADS_PER_BLOCK>>>(heads, out);
}